// round 2
// baseline (speedup 1.0000x reference)
#include <cuda_runtime.h>
#include <cstdint>

// Problem constants (fixed shapes)
#define BATCH 8
#define PH 256
#define PW 256
#define DIN 512
#define C 256            // DIN/2
#define WS 8
#define WH 32            // PH/WS
#define WW 32
#define NPOS (BATCH*WH*WW)   // 8192
#define HEADS 8
#define HD 32
#define QKV3 768

// Scratch (device globals; no allocation allowed)
__device__ float g_uni[NPOS * C];        // 8 MB   (pos-major: [pos][c])
__device__ float g_qkv[NPOS * QKV3];     // 24 MB  ([pos][768] = q|k|v, each h*32+d)
__device__ float g_M[NPOS * 512];        // 16 MB  ([pos][mean_f(256) | mean_b(256)])
__device__ float g_AT[512 * 512];        // combined (proj ∘ merge) matrix, [d][c2]
__device__ float g_cbias[512];

// ---------------------------------------------------------------------------
// Prep: AT[d][c2] = sum_e proj_w[e][c2&255] * merge_w[d][(c2>>8)*256 + e]
// ---------------------------------------------------------------------------
__global__ void prep_acomb(const float* __restrict__ proj_w,
                           const float* __restrict__ merge_w) {
    __shared__ float Pt[16][17];
    __shared__ float Mt[16][17];
    int tx = threadIdx.x, ty = threadIdx.y;
    int d0 = blockIdx.y * 16, c0 = blockIdx.x * 16;
    int sel = c0 >> 8;
    int cbase = c0 & 255;
    float acc = 0.f;
    for (int e0 = 0; e0 < 256; e0 += 16) {
        Pt[ty][tx] = proj_w[(e0 + ty) * 256 + cbase + tx];
        Mt[ty][tx] = merge_w[(d0 + ty) * 512 + sel * 256 + e0 + tx];
        __syncthreads();
#pragma unroll
        for (int k = 0; k < 16; k++) acc += Pt[k][tx] * Mt[ty][k];
        __syncthreads();
    }
    g_AT[(d0 + ty) * 512 + c0 + tx] = acc;
}

__global__ void prep_cbias(const float* __restrict__ proj_b,
                           const float* __restrict__ merge_b,
                           const float* __restrict__ merge_w) {
    int d = blockIdx.x * 128 + threadIdx.x;
    float acc = merge_b[d];
    for (int e = 0; e < 256; e++)
        acc += proj_b[e] * (merge_w[d * 512 + e] + merge_w[d * 512 + 256 + e]);
    g_cbias[d] = acc;
}

// ---------------------------------------------------------------------------
// Grouped conv: uni[pos][c] = sum_{i,kh,kw} x[b, oy*8+kh, ox*8+kw, 2c+i]*w[c,i,kh,kw] + b[c]
// Block = (b, oy, half-of-ox-row); 256 threads = one channel each.
// Weights staged in smem transposed to [tap2][c] (padded 257) for conflict-free reads.
// ---------------------------------------------------------------------------
__global__ void conv_kernel(const float* __restrict__ x,
                            const float* __restrict__ w,
                            const float* __restrict__ wb) {
    extern __shared__ float wsh[];   // [128][257]
    int tid = threadIdx.x;           // 256
    for (int idx = tid; idx < 32768; idx += 256) {
        int c = idx >> 7, r = idx & 127;
        int i = r >> 6, t = r & 63;
        wsh[(t * 2 + i) * 257 + c] = w[idx];
    }
    __syncthreads();

    int blk = blockIdx.x;            // 512 = b(8)*oy(32)*half(2)
    int half = blk & 1;
    int oy = (blk >> 1) & 31;
    int b = blk >> 6;
    int c = tid;
    float bias = wb[c];

    for (int ox = half * 16; ox < half * 16 + 16; ox++) {
        float acc = bias;
#pragma unroll
        for (int kh = 0; kh < 8; kh++) {
            const float* xrow =
                x + ((size_t)((b * 256 + oy * 8 + kh)) * 256 + ox * 8) * 512 + 2 * c;
#pragma unroll
            for (int kw = 0; kw < 8; kw++) {
                float2 xv = *(const float2*)(xrow + kw * 512);
                int t = kh * 8 + kw;
                acc += xv.x * wsh[(t * 2 + 0) * 257 + c]
                     + xv.y * wsh[(t * 2 + 1) * 257 + c];
            }
        }
        g_uni[((size_t)((b * 32 + oy) * 32 + ox)) * 256 + c] = acc;
    }
}

// ---------------------------------------------------------------------------
// Generic fp32 GEMM (C = A @ B^T + bias), 64x64x16 tiles, 4x4 microtile.
// A: (M,K) row-major, B: (N,K) row-major. M = gridDim.y*64, N,K args.
// ---------------------------------------------------------------------------
__device__ __forceinline__ void gemm_nt_body(const float* __restrict__ A,
                                             const float* __restrict__ B,
                                             const float* __restrict__ bias,
                                             float* __restrict__ Cout,
                                             int N, int K) {
    __shared__ float As[16][68];
    __shared__ float Bs[16][68];
    int tid = threadIdx.x;           // 256
    int tx = tid & 15, ty = tid >> 4;
    int m0 = blockIdx.y * 64, n0 = blockIdx.x * 64;
    int lrow = tid >> 2;             // 0..63
    int lk = (tid & 3) * 4;          // 0,4,8,12
    const float* Ap = A + (size_t)(m0 + lrow) * K + lk;
    const float* Bp = B + (size_t)(n0 + lrow) * K + lk;
    float acc[4][4] = {};

    for (int k0 = 0; k0 < K; k0 += 16) {
        float4 av = *(const float4*)(Ap + k0);
        float4 bv = *(const float4*)(Bp + k0);
        As[lk + 0][lrow] = av.x; As[lk + 1][lrow] = av.y;
        As[lk + 2][lrow] = av.z; As[lk + 3][lrow] = av.w;
        Bs[lk + 0][lrow] = bv.x; Bs[lk + 1][lrow] = bv.y;
        Bs[lk + 2][lrow] = bv.z; Bs[lk + 3][lrow] = bv.w;
        __syncthreads();
#pragma unroll
        for (int kk = 0; kk < 16; kk++) {
            float4 a = *(const float4*)&As[kk][ty * 4];
            float4 b = *(const float4*)&Bs[kk][tx * 4];
            acc[0][0] += a.x * b.x; acc[0][1] += a.x * b.y;
            acc[0][2] += a.x * b.z; acc[0][3] += a.x * b.w;
            acc[1][0] += a.y * b.x; acc[1][1] += a.y * b.y;
            acc[1][2] += a.y * b.z; acc[1][3] += a.y * b.w;
            acc[2][0] += a.z * b.x; acc[2][1] += a.z * b.y;
            acc[2][2] += a.z * b.z; acc[2][3] += a.z * b.w;
            acc[3][0] += a.w * b.x; acc[3][1] += a.w * b.y;
            acc[3][2] += a.w * b.z; acc[3][3] += a.w * b.w;
        }
        __syncthreads();
    }
    float4 bb = *(const float4*)&bias[n0 + tx * 4];
#pragma unroll
    for (int u = 0; u < 4; u++) {
        float4 o;
        o.x = acc[u][0] + bb.x;
        o.y = acc[u][1] + bb.y;
        o.z = acc[u][2] + bb.z;
        o.w = acc[u][3] + bb.w;
        *(float4*)&Cout[(size_t)(m0 + ty * 4 + u) * N + n0 + tx * 4] = o;
    }
}

__global__ void gemm_qkv(const float* __restrict__ qkvw, const float* __restrict__ qkvb) {
    gemm_nt_body(g_uni, qkvw, qkvb, g_qkv, QKV3, 256);
}
__global__ void gemm_final(float* __restrict__ out) {
    gemm_nt_body(g_M, g_AT, g_cbias, out, 512, 512);
}

// ---------------------------------------------------------------------------
// Attention: one block per grid position, both contexts (fwd/bwd).
// Gathers the 4 neighbor qkv rows per context, computes 4x4 attention per head,
// means over the 4 query slots, writes g_M[pos][512].
// Skewed smem indexing ((dd+lane)&31) keeps LDS conflict-free.
// ---------------------------------------------------------------------------
__global__ void attn_kernel(const float* __restrict__ relb) {
    __shared__ float tok[8][768];    // [ctx*4 + slot][q|k|v]
    __shared__ float osum[8][256];   // [ctx*4 + n][h*32+d]
    __shared__ float btab[72];       // 9 x 8 heads
    int pos = blockIdx.x;
    int b = pos >> 10, yy = (pos >> 5) & 31, xx = pos & 31;
    int tid = threadIdx.x;           // 128

    if (tid < 72) btab[tid] = relb[tid];
#pragma unroll
    for (int s = 0; s < 4; s++) {
        int i = s >> 1, j = s & 1;
        // fwd padding: p==32 -> 30
        int ry = yy + i; if (ry > 31) ry = 30;
        int rx = xx + j; if (rx > 31) rx = 30;
        const float* src = g_qkv + (size_t)((b * 32 + ry) * 32 + rx) * 768;
        for (int cc = tid; cc < 768; cc += 128) tok[s][cc] = src[cc];
        // bwd padding: p==0 -> 1, else p-1
        int by = yy + i; by = (by == 0) ? 1 : by - 1;
        int bx = xx + j; bx = (bx == 0) ? 1 : bx - 1;
        const float* src2 = g_qkv + (size_t)((b * 32 + by) * 32 + bx) * 768;
        for (int cc = tid; cc < 768; cc += 128) tok[4 + s][cc] = src2[cc];
    }
    __syncthreads();

    {
        int ctx = tid >> 6;          // 0 fwd, 1 bwd
        int r = tid & 63;
        int h = r >> 3;              // 0..7
        int n = (r >> 1) & 3;        // 0..3 (query slot)
        int dh = (r & 1) * 16;       // this thread's half of d for PV
        int lane = tid & 31;
        const float scale = 0.17677669529663687f;   // 32^-0.5

        // q into registers (skewed order, conflict-free)
        float qreg[32];
#pragma unroll
        for (int dd = 0; dd < 32; dd++)
            qreg[dd] = tok[ctx * 4 + n][h * 32 + ((dd + lane) & 31)];

        int ni = n >> 1, nj = n & 1;
        float sc[4];
#pragma unroll
        for (int m = 0; m < 4; m++) {
            int mi = m >> 1, mj = m & 1;
            int ridx = (ni - mi + 1) * 3 + (nj - mj + 1);
            float a = 0.f;
#pragma unroll
            for (int dd = 0; dd < 32; dd++)
                a += qreg[dd] * tok[ctx * 4 + m][256 + h * 32 + ((dd + lane) & 31)];
            sc[m] = a * scale + btab[ridx * 8 + h];
        }
        float mx = fmaxf(fmaxf(sc[0], sc[1]), fmaxf(sc[2], sc[3]));
        float p0 = expf(sc[0] - mx), p1 = expf(sc[1] - mx);
        float p2 = expf(sc[2] - mx), p3 = expf(sc[3] - mx);
        float inv = 1.f / (p0 + p1 + p2 + p3);
        p0 *= inv; p1 *= inv; p2 *= inv; p3 *= inv;

#pragma unroll
        for (int dd = 0; dd < 16; dd++) {
            int d = dh + ((dd + lane) & 15);
            float o = p0 * tok[ctx * 4 + 0][512 + h * 32 + d]
                    + p1 * tok[ctx * 4 + 1][512 + h * 32 + d]
                    + p2 * tok[ctx * 4 + 2][512 + h * 32 + d]
                    + p3 * tok[ctx * 4 + 3][512 + h * 32 + d];
            osum[ctx * 4 + n][h * 32 + d] = o;
        }
    }
    __syncthreads();

    // mean over the 4 query slots; write [mean_f | mean_b]
    float* dst = g_M + (size_t)pos * 512;
    for (int cc = tid; cc < 512; cc += 128) {
        int ctx = cc >> 8, c2 = cc & 255;
        dst[cc] = 0.25f * (osum[ctx * 4 + 0][c2] + osum[ctx * 4 + 1][c2] +
                           osum[ctx * 4 + 2][c2] + osum[ctx * 4 + 3][c2]);
    }
}

// ---------------------------------------------------------------------------
extern "C" void kernel_launch(void* const* d_in, const int* in_sizes, int n_in,
                              void* d_out, int out_size) {
    const float* x      = (const float*)d_in[0];
    const float* uw     = (const float*)d_in[1];
    const float* ub     = (const float*)d_in[2];
    const float* qkvw   = (const float*)d_in[3];
    const float* qkvb   = (const float*)d_in[4];
    const float* relb   = (const float*)d_in[5];
    const float* projw  = (const float*)d_in[6];
    const float* projb  = (const float*)d_in[7];
    const float* mergew = (const float*)d_in[8];
    const float* mergeb = (const float*)d_in[9];
    float* out = (float*)d_out;

    cudaFuncSetAttribute(conv_kernel, cudaFuncAttributeMaxDynamicSharedMemorySize, 131584);

    prep_acomb<<<dim3(32, 32), dim3(16, 16)>>>(projw, mergew);
    prep_cbias<<<4, 128>>>(projb, mergeb, mergew);
    conv_kernel<<<512, 256, 131584>>>(x, uw, ub);
    gemm_qkv<<<dim3(QKV3 / 64, NPOS / 64), 256>>>(qkvw, qkvb);
    attn_kernel<<<NPOS, 128>>>(relb);
    gemm_final<<<dim3(512 / 64, NPOS / 64), 256>>>(out);
}

// round 3
// speedup vs baseline: 1.0379x; 1.0379x over previous
#include <cuda_runtime.h>
#include <cstdint>

// Problem constants (fixed shapes)
#define BATCH 8
#define PH 256
#define PW 256
#define DIN 512
#define C 256            // DIN/2
#define WS 8
#define WH 32            // PH/WS
#define WW 32
#define NPOS (BATCH*WH*WW)   // 8192
#define HEADS 8
#define HD 32
#define QKV3 768

// Scratch (device globals; no allocation allowed)
__device__ float g_uni[NPOS * C];        // 8 MB   (pos-major: [pos][c])
__device__ float g_qkv[NPOS * QKV3];     // 24 MB  ([pos][768] = q|k|v, each h*32+d)
__device__ float g_M[NPOS * 512];        // 16 MB  ([pos][mean_f(256) | mean_b(256)])
__device__ float g_AT[512 * 512];        // combined (proj ∘ merge) matrix, [d][c2]
__device__ float g_cbias[512];

// ---------------------------------------------------------------------------
// Prep: AT[d][c2] = sum_e proj_w[e][c2&255] * merge_w[d][(c2>>8)*256 + e]
// ---------------------------------------------------------------------------
__global__ void prep_acomb(const float* __restrict__ proj_w,
                           const float* __restrict__ merge_w) {
    __shared__ float Pt[16][17];
    __shared__ float Mt[16][17];
    int tx = threadIdx.x, ty = threadIdx.y;
    int d0 = blockIdx.y * 16, c0 = blockIdx.x * 16;
    int sel = c0 >> 8;
    int cbase = c0 & 255;
    float acc = 0.f;
    for (int e0 = 0; e0 < 256; e0 += 16) {
        Pt[ty][tx] = proj_w[(e0 + ty) * 256 + cbase + tx];
        Mt[ty][tx] = merge_w[(d0 + ty) * 512 + sel * 256 + e0 + tx];
        __syncthreads();
#pragma unroll
        for (int k = 0; k < 16; k++) acc += Pt[k][tx] * Mt[ty][k];
        __syncthreads();
    }
    g_AT[(d0 + ty) * 512 + c0 + tx] = acc;
}

__global__ void prep_cbias(const float* __restrict__ proj_b,
                           const float* __restrict__ merge_b,
                           const float* __restrict__ merge_w) {
    int d = blockIdx.x * 128 + threadIdx.x;
    float acc = merge_b[d];
    for (int e = 0; e < 256; e++)
        acc += proj_b[e] * (merge_w[d * 512 + e] + merge_w[d * 512 + 256 + e]);
    g_cbias[d] = acc;
}

// ---------------------------------------------------------------------------
// Grouped conv. 512 threads/block (16 warps) for latency hiding:
//   tid&255 = channel, tid>>8 selects ox-quad group; each thread computes
//   8 outputs as 2 groups of 4 (4 accumulators share each weight LDS).
// Weights staged in smem as [tap*2+i][c] (128 x 256 = 128KB, conflict-free:
// consecutive lanes read consecutive c).
// ---------------------------------------------------------------------------
__global__ void __launch_bounds__(512, 1)
conv_kernel(const float* __restrict__ x,
            const float* __restrict__ w,
            const float* __restrict__ wb) {
    extern __shared__ float wsh[];   // [128][256]
    int tid = threadIdx.x;           // 512
    for (int idx = tid; idx < 32768; idx += 512) {
        int c = idx >> 7, r = idx & 127;
        int i = r >> 6, t = r & 63;
        wsh[(t * 2 + i) * 256 + c] = w[idx];
    }
    __syncthreads();

    int blk = blockIdx.x;            // 512 = b(8)*oy(32)*half(2)
    int half = blk & 1;
    int oy = (blk >> 1) & 31;
    int b = blk >> 6;
    int c = tid & 255;
    int oxq = tid >> 8;              // 0..1
    float bias = wb[c];

#pragma unroll
    for (int g = 0; g < 2; g++) {
        int ox0 = half * 16 + oxq * 8 + g * 4;
        float acc0 = bias, acc1 = bias, acc2 = bias, acc3 = bias;
#pragma unroll
        for (int kh = 0; kh < 8; kh++) {
            const float* xr =
                x + ((size_t)(b * 256 + oy * 8 + kh) * 256 + ox0 * 8) * 512 + 2 * c;
#pragma unroll
            for (int kw = 0; kw < 8; kw++) {
                float w0 = wsh[((kh * 8 + kw) * 2 + 0) * 256 + c];
                float w1 = wsh[((kh * 8 + kw) * 2 + 1) * 256 + c];
                float2 x0 = *(const float2*)(xr + (0 * 8 + kw) * 512);
                float2 x1 = *(const float2*)(xr + (1 * 8 + kw) * 512);
                float2 x2 = *(const float2*)(xr + (2 * 8 + kw) * 512);
                float2 x3 = *(const float2*)(xr + (3 * 8 + kw) * 512);
                acc0 += x0.x * w0 + x0.y * w1;
                acc1 += x1.x * w0 + x1.y * w1;
                acc2 += x2.x * w0 + x2.y * w1;
                acc3 += x3.x * w0 + x3.y * w1;
            }
        }
        size_t base = (size_t)((b * 32 + oy) * 32 + ox0) * 256 + c;
        g_uni[base + 0 * 256] = acc0;
        g_uni[base + 1 * 256] = acc1;
        g_uni[base + 2 * 256] = acc2;
        g_uni[base + 3 * 256] = acc3;
    }
}

// ---------------------------------------------------------------------------
// fp32 GEMM (C = A @ B^T + bias), 128x64 block tile, k-tile 16,
// 8x4 microtile per thread, register-prefetch double buffering.
// A: (M,K) row-major, B: (N,K) row-major. K multiple of 16.
// ---------------------------------------------------------------------------
__device__ __forceinline__ void gemm_nt_body(const float* __restrict__ A,
                                             const float* __restrict__ B,
                                             const float* __restrict__ bias,
                                             float* __restrict__ Cout,
                                             int N, int K) {
    __shared__ float As[16][132];    // [k][m], pad to 132
    __shared__ float Bs[16][68];     // [k][n]
    int tid = threadIdx.x;           // 256
    int tx = tid & 15;               // n block: 4 cols
    int ty = tid >> 4;               // m block: 8 rows
    int m0 = blockIdx.y * 128, n0 = blockIdx.x * 64;

    int arow = tid >> 1;             // 0..127
    int ak = (tid & 1) * 8;          // 0 or 8
    int brow = tid >> 2;             // 0..63
    int bk = (tid & 3) * 4;          // 0,4,8,12

    const float* Ap = A + (size_t)(m0 + arow) * K + ak;
    const float* Bp = B + (size_t)(n0 + brow) * K + bk;

    float acc[8][4] = {};
    float4 pa0 = *(const float4*)(Ap + 0);
    float4 pa1 = *(const float4*)(Ap + 4);
    float4 pb  = *(const float4*)(Bp + 0);

    for (int k0 = 0; k0 < K; k0 += 16) {
        As[ak + 0][arow] = pa0.x; As[ak + 1][arow] = pa0.y;
        As[ak + 2][arow] = pa0.z; As[ak + 3][arow] = pa0.w;
        As[ak + 4][arow] = pa1.x; As[ak + 5][arow] = pa1.y;
        As[ak + 6][arow] = pa1.z; As[ak + 7][arow] = pa1.w;
        Bs[bk + 0][brow] = pb.x;  Bs[bk + 1][brow] = pb.y;
        Bs[bk + 2][brow] = pb.z;  Bs[bk + 3][brow] = pb.w;
        __syncthreads();
        if (k0 + 16 < K) {
            pa0 = *(const float4*)(Ap + k0 + 16);
            pa1 = *(const float4*)(Ap + k0 + 20);
            pb  = *(const float4*)(Bp + k0 + 16);
        }
#pragma unroll
        for (int kk = 0; kk < 16; kk++) {
            float4 a0 = *(const float4*)&As[kk][ty * 8];
            float4 a1 = *(const float4*)&As[kk][ty * 8 + 4];
            float4 b  = *(const float4*)&Bs[kk][tx * 4];
            float am[8] = {a0.x, a0.y, a0.z, a0.w, a1.x, a1.y, a1.z, a1.w};
#pragma unroll
            for (int u = 0; u < 8; u++) {
                acc[u][0] += am[u] * b.x;
                acc[u][1] += am[u] * b.y;
                acc[u][2] += am[u] * b.z;
                acc[u][3] += am[u] * b.w;
            }
        }
        __syncthreads();
    }
    float4 bb = *(const float4*)&bias[n0 + tx * 4];
#pragma unroll
    for (int u = 0; u < 8; u++) {
        float4 o;
        o.x = acc[u][0] + bb.x;
        o.y = acc[u][1] + bb.y;
        o.z = acc[u][2] + bb.z;
        o.w = acc[u][3] + bb.w;
        *(float4*)&Cout[(size_t)(m0 + ty * 8 + u) * N + n0 + tx * 4] = o;
    }
}

__global__ void __launch_bounds__(256)
gemm_qkv(const float* __restrict__ qkvw, const float* __restrict__ qkvb) {
    gemm_nt_body(g_uni, qkvw, qkvb, g_qkv, QKV3, 256);
}
__global__ void __launch_bounds__(256)
gemm_final(float* __restrict__ out) {
    gemm_nt_body(g_M, g_AT, g_cbias, out, 512, 512);
}

// ---------------------------------------------------------------------------
// Attention: one block per grid position, both contexts (fwd/bwd).
// ---------------------------------------------------------------------------
__global__ void attn_kernel(const float* __restrict__ relb) {
    __shared__ float tok[8][768];    // [ctx*4 + slot][q|k|v]
    __shared__ float osum[8][256];   // [ctx*4 + n][h*32+d]
    __shared__ float btab[72];       // 9 x 8 heads
    int pos = blockIdx.x;
    int b = pos >> 10, yy = (pos >> 5) & 31, xx = pos & 31;
    int tid = threadIdx.x;           // 128

    if (tid < 72) btab[tid] = relb[tid];
#pragma unroll
    for (int s = 0; s < 4; s++) {
        int i = s >> 1, j = s & 1;
        // fwd padding: p==32 -> 30
        int ry = yy + i; if (ry > 31) ry = 30;
        int rx = xx + j; if (rx > 31) rx = 30;
        const float* src = g_qkv + (size_t)((b * 32 + ry) * 32 + rx) * 768;
        for (int cc = tid; cc < 768; cc += 128) tok[s][cc] = src[cc];
        // bwd padding: p==0 -> 1, else p-1
        int by = yy + i; by = (by == 0) ? 1 : by - 1;
        int bx = xx + j; bx = (bx == 0) ? 1 : bx - 1;
        const float* src2 = g_qkv + (size_t)((b * 32 + by) * 32 + bx) * 768;
        for (int cc = tid; cc < 768; cc += 128) tok[4 + s][cc] = src2[cc];
    }
    __syncthreads();

    {
        int ctx = tid >> 6;          // 0 fwd, 1 bwd
        int r = tid & 63;
        int h = r >> 3;              // 0..7
        int n = (r >> 1) & 3;        // 0..3 (query slot)
        int dh = (r & 1) * 16;       // this thread's half of d for PV
        int lane = tid & 31;
        const float scale = 0.17677669529663687f;   // 32^-0.5

        float qreg[32];
#pragma unroll
        for (int dd = 0; dd < 32; dd++)
            qreg[dd] = tok[ctx * 4 + n][h * 32 + ((dd + lane) & 31)];

        int ni = n >> 1, nj = n & 1;
        float sc[4];
#pragma unroll
        for (int m = 0; m < 4; m++) {
            int mi = m >> 1, mj = m & 1;
            int ridx = (ni - mi + 1) * 3 + (nj - mj + 1);
            float a = 0.f;
#pragma unroll
            for (int dd = 0; dd < 32; dd++)
                a += qreg[dd] * tok[ctx * 4 + m][256 + h * 32 + ((dd + lane) & 31)];
            sc[m] = a * scale + btab[ridx * 8 + h];
        }
        float mx = fmaxf(fmaxf(sc[0], sc[1]), fmaxf(sc[2], sc[3]));
        float p0 = expf(sc[0] - mx), p1 = expf(sc[1] - mx);
        float p2 = expf(sc[2] - mx), p3 = expf(sc[3] - mx);
        float inv = 1.f / (p0 + p1 + p2 + p3);
        p0 *= inv; p1 *= inv; p2 *= inv; p3 *= inv;

#pragma unroll
        for (int dd = 0; dd < 16; dd++) {
            int d = dh + ((dd + lane) & 15);
            float o = p0 * tok[ctx * 4 + 0][512 + h * 32 + d]
                    + p1 * tok[ctx * 4 + 1][512 + h * 32 + d]
                    + p2 * tok[ctx * 4 + 2][512 + h * 32 + d]
                    + p3 * tok[ctx * 4 + 3][512 + h * 32 + d];
            osum[ctx * 4 + n][h * 32 + d] = o;
        }
    }
    __syncthreads();

    float* dst = g_M + (size_t)pos * 512;
    for (int cc = tid; cc < 512; cc += 128) {
        int ctx = cc >> 8, c2 = cc & 255;
        dst[cc] = 0.25f * (osum[ctx * 4 + 0][c2] + osum[ctx * 4 + 1][c2] +
                           osum[ctx * 4 + 2][c2] + osum[ctx * 4 + 3][c2]);
    }
}

// ---------------------------------------------------------------------------
extern "C" void kernel_launch(void* const* d_in, const int* in_sizes, int n_in,
                              void* d_out, int out_size) {
    const float* x      = (const float*)d_in[0];
    const float* uw     = (const float*)d_in[1];
    const float* ub     = (const float*)d_in[2];
    const float* qkvw   = (const float*)d_in[3];
    const float* qkvb   = (const float*)d_in[4];
    const float* relb   = (const float*)d_in[5];
    const float* projw  = (const float*)d_in[6];
    const float* projb  = (const float*)d_in[7];
    const float* mergew = (const float*)d_in[8];
    const float* mergeb = (const float*)d_in[9];
    float* out = (float*)d_out;

    cudaFuncSetAttribute(conv_kernel, cudaFuncAttributeMaxDynamicSharedMemorySize, 131072);

    prep_acomb<<<dim3(32, 32), dim3(16, 16)>>>(projw, mergew);
    prep_cbias<<<4, 128>>>(projb, mergeb, mergew);
    conv_kernel<<<512, 512, 131072>>>(x, uw, ub);
    gemm_qkv<<<dim3(QKV3 / 64, NPOS / 128), 256>>>(qkvw, qkvb);
    attn_kernel<<<NPOS, 128>>>(relb);
    gemm_final<<<dim3(512 / 64, NPOS / 128), 256>>>(out);
}

// round 5
// speedup vs baseline: 1.2184x; 1.1739x over previous
#include <cuda_runtime.h>
#include <cstdint>

// Problem constants (fixed shapes)
#define BATCH 8
#define PH 256
#define PW 256
#define DIN 512
#define C 256            // DIN/2
#define WS 8
#define WH 32            // PH/WS
#define WW 32
#define NPOS (BATCH*WH*WW)   // 8192
#define HEADS 8
#define HD 32
#define QKV3 768

// Scratch (device globals; no allocation allowed)
__device__ float g_uni[NPOS * C];        // 8 MB   (pos-major: [pos][c])
__device__ float g_qkv[NPOS * QKV3];     // 24 MB  ([pos][768] = q|k|v, each h*32+d)
__device__ float g_M[NPOS * 512];        // 16 MB  ([pos][mean_f(256) | mean_b(256)])
__device__ float g_AT[512 * 512];        // combined (proj ∘ merge) matrix, [d][c2]
__device__ float g_cbias[512];

// ---------------------------------------------------------------------------
// Prep: AT[d][c2] = sum_e proj_w[e][c2&255] * merge_w[d][(c2>>8)*256 + e]
// ---------------------------------------------------------------------------
__global__ void prep_acomb(const float* __restrict__ proj_w,
                           const float* __restrict__ merge_w) {
    __shared__ float Pt[16][17];
    __shared__ float Mt[16][17];
    int tx = threadIdx.x, ty = threadIdx.y;
    int d0 = blockIdx.y * 16, c0 = blockIdx.x * 16;
    int sel = c0 >> 8;
    int cbase = c0 & 255;
    float acc = 0.f;
    for (int e0 = 0; e0 < 256; e0 += 16) {
        Pt[ty][tx] = proj_w[(e0 + ty) * 256 + cbase + tx];
        Mt[ty][tx] = merge_w[(d0 + ty) * 512 + sel * 256 + e0 + tx];
        __syncthreads();
#pragma unroll
        for (int k = 0; k < 16; k++) acc += Pt[k][tx] * Mt[ty][k];
        __syncthreads();
    }
    g_AT[(d0 + ty) * 512 + c0 + tx] = acc;
}

__global__ void prep_cbias(const float* __restrict__ proj_b,
                           const float* __restrict__ merge_b,
                           const float* __restrict__ merge_w) {
    int d = blockIdx.x * 128 + threadIdx.x;
    float acc = merge_b[d];
    for (int e = 0; e < 256; e++)
        acc += proj_b[e] * (merge_w[d * 512 + e] + merge_w[d * 512 + 256 + e]);
    g_cbias[d] = acc;
}

// ---------------------------------------------------------------------------
// Grouped conv, v3. Block = (b, oy, channel-half). 512 threads:
//   cg = tid&63   -> this thread's pair of output channels (4 input channels)
//   oxq = tid>>6  -> 4-wide ox group (8 groups = full 32-ox row)
// Each thread: 4 ox outputs x 2 channels, float4 global loads (16B),
// float4 weight LDS. Smem = 64 taps x 256 floats = 64KB -> 2-3 blocks/SM.
// wsh[t*256 + cl*2 + i] = w[(chalf*128+cl)*128 + i*64 + t]
// ---------------------------------------------------------------------------
__global__ void __launch_bounds__(512)
conv_kernel(const float* __restrict__ x,
            const float* __restrict__ w,
            const float* __restrict__ wb) {
    extern __shared__ float wsh[];   // [64][256]
    int tid = threadIdx.x;           // 512
    int blk = blockIdx.x;            // 512 = b(8)*oy(32)*chalf(2)
    int chalf = blk & 1;
    int oy = (blk >> 1) & 31;
    int b = blk >> 6;

    for (int idx = tid; idx < 16384; idx += 512) {
        int t = idx >> 8;            // 0..63
        int r = idx & 255;           // cl*2 + i
        int cl = r >> 1, i = r & 1;
        wsh[idx] = w[(chalf * 128 + cl) * 128 + i * 64 + t];
    }
    __syncthreads();

    int cg = tid & 63;               // out chans: chalf*128 + 2cg, +1
    int oxq = tid >> 6;              // 0..7
    int ox0 = oxq * 4;
    int cout0 = chalf * 128 + cg * 2;
    int cin0 = chalf * 256 + cg * 4; // input channel offset

    float b0 = wb[cout0], b1 = wb[cout0 + 1];
    float a0x = b0, a0y = b1, a1x = b0, a1y = b1;
    float a2x = b0, a2y = b1, a3x = b0, a3y = b1;

#pragma unroll
    for (int kh = 0; kh < 8; kh++) {
        const float* xr =
            x + ((size_t)(b * 256 + oy * 8 + kh) * 256 + ox0 * 8) * 512 + cin0;
#pragma unroll
        for (int kw = 0; kw < 8; kw++) {
            float4 wv = *(const float4*)&wsh[(kh * 8 + kw) * 256 + cg * 4];
            float4 x0 = *(const float4*)(xr + (0 * 8 + kw) * 512);
            float4 x1 = *(const float4*)(xr + (1 * 8 + kw) * 512);
            float4 x2 = *(const float4*)(xr + (2 * 8 + kw) * 512);
            float4 x3 = *(const float4*)(xr + (3 * 8 + kw) * 512);
            a0x += x0.x * wv.x + x0.y * wv.y;  a0y += x0.z * wv.z + x0.w * wv.w;
            a1x += x1.x * wv.x + x1.y * wv.y;  a1y += x1.z * wv.z + x1.w * wv.w;
            a2x += x2.x * wv.x + x2.y * wv.y;  a2y += x2.z * wv.z + x2.w * wv.w;
            a3x += x3.x * wv.x + x3.y * wv.y;  a3y += x3.z * wv.z + x3.w * wv.w;
        }
    }
    size_t base = (size_t)((b * 32 + oy) * 32 + ox0) * 256 + cout0;
    *(float2*)&g_uni[base + 0 * 256] = make_float2(a0x, a0y);
    *(float2*)&g_uni[base + 1 * 256] = make_float2(a1x, a1y);
    *(float2*)&g_uni[base + 2 * 256] = make_float2(a2x, a2y);
    *(float2*)&g_uni[base + 3 * 256] = make_float2(a3x, a3y);
}

// ---------------------------------------------------------------------------
// fp32 GEMM (C = A @ B^T + bias), 128x128 block tile, k-tile 8, 8x8 microtile,
// smem double buffering with ONE sync per k-tile.
// A: (M,K) row-major, B: (N,K) row-major. K % 8 == 0, M % 128 == 0, N % 128 == 0.
// ---------------------------------------------------------------------------
__device__ __forceinline__ void gemm_nt_body(const float* __restrict__ A,
                                             const float* __restrict__ B,
                                             const float* __restrict__ bias,
                                             float* __restrict__ Cout,
                                             int N, int K) {
    __shared__ float As[2][8][132];
    __shared__ float Bs[2][8][132];
    int tid = threadIdx.x;           // 256
    int m0 = blockIdx.y * 128, n0 = blockIdx.x * 128;

    int ldrow = tid >> 1;            // 0..127
    int ldk = (tid & 1) * 4;         // 0 or 4
    const float* Ap = A + (size_t)(m0 + ldrow) * K + ldk;
    const float* Bp = B + (size_t)(n0 + ldrow) * K + ldk;

    int warp = tid >> 5, lane = tid & 31;
    int wm = (warp >> 2) * 64 + (lane >> 2) * 8;   // m offset within tile
    int wn = (warp & 3) * 32 + (lane & 3) * 8;     // n offset within tile

    float acc[8][8] = {};

    // preload tile 0
    float4 pa = *(const float4*)Ap;
    float4 pb = *(const float4*)Bp;
    As[0][ldk + 0][ldrow] = pa.x; As[0][ldk + 1][ldrow] = pa.y;
    As[0][ldk + 2][ldrow] = pa.z; As[0][ldk + 3][ldrow] = pa.w;
    Bs[0][ldk + 0][ldrow] = pb.x; Bs[0][ldk + 1][ldrow] = pb.y;
    Bs[0][ldk + 2][ldrow] = pb.z; Bs[0][ldk + 3][ldrow] = pb.w;
    __syncthreads();

    int p = 0;
    int T = K >> 3;
    for (int t = 0; t < T; t++) {
        if (t + 1 < T) {
            pa = *(const float4*)(Ap + (t + 1) * 8);
            pb = *(const float4*)(Bp + (t + 1) * 8);
        }
#pragma unroll
        for (int kk = 0; kk < 8; kk++) {
            float4 A0 = *(const float4*)&As[p][kk][wm];
            float4 A1 = *(const float4*)&As[p][kk][wm + 4];
            float4 B0 = *(const float4*)&Bs[p][kk][wn];
            float4 B1 = *(const float4*)&Bs[p][kk][wn + 4];
            float av[8] = {A0.x, A0.y, A0.z, A0.w, A1.x, A1.y, A1.z, A1.w};
            float bv[8] = {B0.x, B0.y, B0.z, B0.w, B1.x, B1.y, B1.z, B1.w};
#pragma unroll
            for (int u = 0; u < 8; u++)
#pragma unroll
                for (int v = 0; v < 8; v++)
                    acc[u][v] += av[u] * bv[v];
        }
        if (t + 1 < T) {
            int q = p ^ 1;
            As[q][ldk + 0][ldrow] = pa.x; As[q][ldk + 1][ldrow] = pa.y;
            As[q][ldk + 2][ldrow] = pa.z; As[q][ldk + 3][ldrow] = pa.w;
            Bs[q][ldk + 0][ldrow] = pb.x; Bs[q][ldk + 1][ldrow] = pb.y;
            Bs[q][ldk + 2][ldrow] = pb.z; Bs[q][ldk + 3][ldrow] = pb.w;
            __syncthreads();
            p = q;
        }
    }

    float4 bb0 = *(const float4*)&bias[n0 + wn];
    float4 bb1 = *(const float4*)&bias[n0 + wn + 4];
    float bvv[8] = {bb0.x, bb0.y, bb0.z, bb0.w, bb1.x, bb1.y, bb1.z, bb1.w};
#pragma unroll
    for (int u = 0; u < 8; u++) {
        float* dst = &Cout[(size_t)(m0 + wm + u) * N + n0 + wn];
        float4 o0 = make_float4(acc[u][0] + bvv[0], acc[u][1] + bvv[1],
                                acc[u][2] + bvv[2], acc[u][3] + bvv[3]);
        float4 o1 = make_float4(acc[u][4] + bvv[4], acc[u][5] + bvv[5],
                                acc[u][6] + bvv[6], acc[u][7] + bvv[7]);
        *(float4*)dst = o0;
        *(float4*)(dst + 4) = o1;
    }
}

__global__ void __launch_bounds__(256)
gemm_qkv(const float* __restrict__ qkvw, const float* __restrict__ qkvb) {
    gemm_nt_body(g_uni, qkvw, qkvb, g_qkv, QKV3, 256);
}
__global__ void __launch_bounds__(256)
gemm_final(float* __restrict__ out) {
    gemm_nt_body(g_M, g_AT, g_cbias, out, 512, 512);
}

// ---------------------------------------------------------------------------
// Attention: one block per grid position, both contexts (fwd/bwd).
// ---------------------------------------------------------------------------
__global__ void attn_kernel(const float* __restrict__ relb) {
    __shared__ float tok[8][768];    // [ctx*4 + slot][q|k|v]
    __shared__ float osum[8][256];   // [ctx*4 + n][h*32+d]
    __shared__ float btab[72];       // 9 x 8 heads
    int pos = blockIdx.x;
    int b = pos >> 10, yy = (pos >> 5) & 31, xx = pos & 31;
    int tid = threadIdx.x;           // 128

    if (tid < 72) btab[tid] = relb[tid];
#pragma unroll
    for (int s = 0; s < 4; s++) {
        int i = s >> 1, j = s & 1;
        // fwd padding: p==32 -> 30
        int ry = yy + i; if (ry > 31) ry = 30;
        int rx = xx + j; if (rx > 31) rx = 30;
        const float* src = g_qkv + (size_t)((b * 32 + ry) * 32 + rx) * 768;
        for (int cc = tid; cc < 768; cc += 128) tok[s][cc] = src[cc];
        // bwd padding: p==0 -> 1, else p-1
        int by = yy + i; by = (by == 0) ? 1 : by - 1;
        int bx = xx + j; bx = (bx == 0) ? 1 : bx - 1;
        const float* src2 = g_qkv + (size_t)((b * 32 + by) * 32 + bx) * 768;
        for (int cc = tid; cc < 768; cc += 128) tok[4 + s][cc] = src2[cc];
    }
    __syncthreads();

    {
        int ctx = tid >> 6;          // 0 fwd, 1 bwd
        int r = tid & 63;
        int h = r >> 3;              // 0..7
        int n = (r >> 1) & 3;        // 0..3 (query slot)
        int dh = (r & 1) * 16;       // this thread's half of d for PV
        int lane = tid & 31;
        const float scale = 0.17677669529663687f;   // 32^-0.5

        float qreg[32];
#pragma unroll
        for (int dd = 0; dd < 32; dd++)
            qreg[dd] = tok[ctx * 4 + n][h * 32 + ((dd + lane) & 31)];

        int ni = n >> 1, nj = n & 1;
        float sc[4];
#pragma unroll
        for (int m = 0; m < 4; m++) {
            int mi = m >> 1, mj = m & 1;
            int ridx = (ni - mi + 1) * 3 + (nj - mj + 1);
            float a = 0.f;
#pragma unroll
            for (int dd = 0; dd < 32; dd++)
                a += qreg[dd] * tok[ctx * 4 + m][256 + h * 32 + ((dd + lane) & 31)];
            sc[m] = a * scale + btab[ridx * 8 + h];
        }
        float mx = fmaxf(fmaxf(sc[0], sc[1]), fmaxf(sc[2], sc[3]));
        float p0 = expf(sc[0] - mx), p1 = expf(sc[1] - mx);
        float p2 = expf(sc[2] - mx), p3 = expf(sc[3] - mx);
        float inv = 1.f / (p0 + p1 + p2 + p3);
        p0 *= inv; p1 *= inv; p2 *= inv; p3 *= inv;

#pragma unroll
        for (int dd = 0; dd < 16; dd++) {
            int d = dh + ((dd + lane) & 15);
            float o = p0 * tok[ctx * 4 + 0][512 + h * 32 + d]
                    + p1 * tok[ctx * 4 + 1][512 + h * 32 + d]
                    + p2 * tok[ctx * 4 + 2][512 + h * 32 + d]
                    + p3 * tok[ctx * 4 + 3][512 + h * 32 + d];
            osum[ctx * 4 + n][h * 32 + d] = o;
        }
    }
    __syncthreads();

    float* dst = g_M + (size_t)pos * 512;
    for (int cc = tid; cc < 512; cc += 128) {
        int ctx = cc >> 8, c2 = cc & 255;
        dst[cc] = 0.25f * (osum[ctx * 4 + 0][c2] + osum[ctx * 4 + 1][c2] +
                           osum[ctx * 4 + 2][c2] + osum[ctx * 4 + 3][c2]);
    }
}

// ---------------------------------------------------------------------------
extern "C" void kernel_launch(void* const* d_in, const int* in_sizes, int n_in,
                              void* d_out, int out_size) {
    const float* x      = (const float*)d_in[0];
    const float* uw     = (const float*)d_in[1];
    const float* ub     = (const float*)d_in[2];
    const float* qkvw   = (const float*)d_in[3];
    const float* qkvb   = (const float*)d_in[4];
    const float* relb   = (const float*)d_in[5];
    const float* projw  = (const float*)d_in[6];
    const float* projb  = (const float*)d_in[7];
    const float* mergew = (const float*)d_in[8];
    const float* mergeb = (const float*)d_in[9];
    float* out = (float*)d_out;

    cudaFuncSetAttribute(conv_kernel, cudaFuncAttributeMaxDynamicSharedMemorySize, 65536);

    prep_acomb<<<dim3(32, 32), dim3(16, 16)>>>(projw, mergew);
    prep_cbias<<<4, 128>>>(projb, mergeb, mergew);
    conv_kernel<<<512, 512, 65536>>>(x, uw, ub);
    gemm_qkv<<<dim3(QKV3 / 128, NPOS / 128), 256>>>(qkvw, qkvb);
    attn_kernel<<<NPOS, 128>>>(relb);
    gemm_final<<<dim3(512 / 128, NPOS / 128), 256>>>(out);
}

// round 6
// speedup vs baseline: 1.3027x; 1.0692x over previous
#include <cuda_runtime.h>
#include <cuda_bf16.h>
#include <cstdint>

// Problem constants (fixed shapes)
#define BATCH 8
#define NPOS 8192            // 8*32*32
#define HEADS 8
#define HD 32
#define QKV3 768
#define CC 256

// Scratch (device globals; no allocation allowed)
__device__ __nv_bfloat16 g_uniS[NPOS * 512];   // [pos][hi(256)|lo(256)]
__device__ __nv_bfloat16 g_qwS[QKV3 * 512];    // [n][hi(256)|lo(256)]
__device__ float g_qkv[NPOS * QKV3];           // fp32 qkv
__device__ __nv_bfloat16 g_MS[NPOS * 1024];    // [pos][hi(512)|lo(512)]
__device__ __nv_bfloat16 g_ATS[512 * 1024];    // combined proj∘merge, [d][hi|lo]
__device__ float g_cbias[512];

__device__ __forceinline__ void bf16split(float v, __nv_bfloat16& hi, __nv_bfloat16& lo) {
    hi = __float2bfloat16_rn(v);
    lo = __float2bfloat16_rn(v - __bfloat162float(hi));
}

// ---------------------------------------------------------------------------
// Prep: AT[d][c2] = sum_e proj_w[e][c2&255] * merge_w[d][(c2>>8)*256 + e]
// writes split-bf16 planes into g_ATS.
// ---------------------------------------------------------------------------
__global__ void prep_acomb(const float* __restrict__ proj_w,
                           const float* __restrict__ merge_w) {
    __shared__ float Pt[16][17];
    __shared__ float Mt[16][17];
    int tx = threadIdx.x, ty = threadIdx.y;
    int d0 = blockIdx.y * 16, c0 = blockIdx.x * 16;
    int sel = c0 >> 8;
    int cbase = c0 & 255;
    float acc = 0.f;
    for (int e0 = 0; e0 < 256; e0 += 16) {
        Pt[ty][tx] = proj_w[(e0 + ty) * 256 + cbase + tx];
        Mt[ty][tx] = merge_w[(d0 + ty) * 512 + sel * 256 + e0 + tx];
        __syncthreads();
#pragma unroll
        for (int k = 0; k < 16; k++) acc += Pt[k][tx] * Mt[ty][k];
        __syncthreads();
    }
    __nv_bfloat16 hi, lo; bf16split(acc, hi, lo);
    g_ATS[(d0 + ty) * 1024 + (c0 + tx)] = hi;
    g_ATS[(d0 + ty) * 1024 + 512 + (c0 + tx)] = lo;
}

__global__ void prep_cbias(const float* __restrict__ proj_b,
                           const float* __restrict__ merge_b,
                           const float* __restrict__ merge_w) {
    int d = blockIdx.x * 128 + threadIdx.x;
    float acc = merge_b[d];
    for (int e = 0; e < 256; e++)
        acc += proj_b[e] * (merge_w[d * 512 + e] + merge_w[d * 512 + 256 + e]);
    g_cbias[d] = acc;
}

__global__ void cvt_qkvw(const float* __restrict__ w) {
    int i = blockIdx.x * 256 + threadIdx.x;      // 768*256
    int n = i >> 8, k = i & 255;
    __nv_bfloat16 hi, lo; bf16split(w[i], hi, lo);
    g_qwS[n * 512 + k] = hi;
    g_qwS[n * 512 + 256 + k] = lo;
}

// ---------------------------------------------------------------------------
// Grouped conv, quarter-channel blocks for occupancy.
// Block = (b, oy, cq). 256 threads: cg=tid&31 (pair of out chans), oxq=tid>>5.
// Each thread: 4 ox x 2 out-channels, float4 global loads.
// Smem weights 64 taps x 128 floats = 32KB.
// Epilogue writes split-bf16 into g_uniS.
// ---------------------------------------------------------------------------
__global__ void __launch_bounds__(256, 3)
conv_kernel(const float* __restrict__ x,
            const float* __restrict__ w,
            const float* __restrict__ wb) {
    extern __shared__ float wsh[];   // [64][128]
    int tid = threadIdx.x;           // 256
    int blk = blockIdx.x;            // 1024 = b(8)*oy(32)*cq(4)
    int cq = blk & 3;
    int oy = (blk >> 2) & 31;
    int b = blk >> 7;

    for (int idx = tid; idx < 8192; idx += 256) {
        int t = idx >> 7;            // 0..63
        int r = idx & 127;
        int cl = r >> 1, i = r & 1;
        wsh[idx] = w[(cq * 64 + cl) * 128 + i * 64 + t];
    }
    __syncthreads();

    int cg = tid & 31;
    int oxq = tid >> 5;              // 0..7
    int ox0 = oxq * 4;
    int cout0 = cq * 64 + cg * 2;
    int cin0 = cq * 128 + cg * 4;

    float b0 = wb[cout0], b1 = wb[cout0 + 1];
    float a0x = b0, a0y = b1, a1x = b0, a1y = b1;
    float a2x = b0, a2y = b1, a3x = b0, a3y = b1;

#pragma unroll
    for (int kh = 0; kh < 8; kh++) {
        const float* xr =
            x + ((size_t)(b * 256 + oy * 8 + kh) * 256 + ox0 * 8) * 512 + cin0;
#pragma unroll
        for (int kw = 0; kw < 8; kw++) {
            float4 wv = *(const float4*)&wsh[(kh * 8 + kw) * 128 + cg * 4];
            float4 x0 = *(const float4*)(xr + (0 * 8 + kw) * 512);
            float4 x1 = *(const float4*)(xr + (1 * 8 + kw) * 512);
            float4 x2 = *(const float4*)(xr + (2 * 8 + kw) * 512);
            float4 x3 = *(const float4*)(xr + (3 * 8 + kw) * 512);
            a0x += x0.x * wv.x + x0.y * wv.y;  a0y += x0.z * wv.z + x0.w * wv.w;
            a1x += x1.x * wv.x + x1.y * wv.y;  a1y += x1.z * wv.z + x1.w * wv.w;
            a2x += x2.x * wv.x + x2.y * wv.y;  a2y += x2.z * wv.z + x2.w * wv.w;
            a3x += x3.x * wv.x + x3.y * wv.y;  a3y += x3.z * wv.z + x3.w * wv.w;
        }
    }
    int pos0 = (b * 32 + oy) * 32 + ox0;
    float av[4][2] = {{a0x, a0y}, {a1x, a1y}, {a2x, a2y}, {a3x, a3y}};
#pragma unroll
    for (int u = 0; u < 4; u++) {
        __nv_bfloat16 h0, l0, h1, l1;
        bf16split(av[u][0], h0, l0);
        bf16split(av[u][1], h1, l1);
        size_t base = (size_t)(pos0 + u) * 512;
        *(__nv_bfloat162*)&g_uniS[base + cout0] = __nv_bfloat162(h0, h1);
        *(__nv_bfloat162*)&g_uniS[base + 256 + cout0] = __nv_bfloat162(l0, l1);
    }
}

// ---------------------------------------------------------------------------
// Split-bf16 tensor-core GEMM: C = A@B^T + bias, exact-ish via 3 segments
//   [Ahi|Ahi|Alo] x [Bhi|Blo|Bhi]  over concatenated k-axis.
// A2: (M, 2K) bf16 (hi plane then lo plane). B2: (N, 2K) bf16. C fp32 (M,N).
// Block tile 128x128, 8 warps (warp tile 32x64), k-chunk 16, double buffered.
// ---------------------------------------------------------------------------
__device__ __forceinline__ void mma16816(float* d, const uint32_t* a,
                                         uint32_t b0, uint32_t b1) {
    asm volatile(
        "mma.sync.aligned.m16n8k16.row.col.f32.bf16.bf16.f32 "
        "{%0,%1,%2,%3}, {%4,%5,%6,%7}, {%8,%9}, {%0,%1,%2,%3};\n"
        : "+f"(d[0]), "+f"(d[1]), "+f"(d[2]), "+f"(d[3])
        : "r"(a[0]), "r"(a[1]), "r"(a[2]), "r"(a[3]), "r"(b0), "r"(b1));
}

template <int K, int KSH>   // K = 256 (KSH=4) or 512 (KSH=5): chunks/seg = K/16
__device__ __forceinline__ void gemm_bf16_body(const __nv_bfloat16* __restrict__ A2,
                                               const __nv_bfloat16* __restrict__ B2,
                                               const float* __restrict__ bias,
                                               float* __restrict__ Cout, int N) {
    __shared__ __nv_bfloat16 As[2][128][20];   // 16 data + 4 pad (40B rows)
    __shared__ __nv_bfloat16 Bs[2][128][20];
    int tid = threadIdx.x;            // 256
    int m0 = blockIdx.y * 128, n0 = blockIdx.x * 128;

    int row = tid >> 1;               // 0..127
    int half = tid & 1;               // 0..1 (8 bf16 each)
    const __nv_bfloat16* Ap = A2 + (size_t)(m0 + row) * (2 * K) + half * 8;
    const __nv_bfloat16* Bp = B2 + (size_t)(n0 + row) * (2 * K) + half * 8;

    int warp = tid >> 5, lane = tid & 31;
    int warp_m = warp & 3, warp_n = warp >> 2;
    int quad = lane >> 2, tid4 = lane & 3;

    float acc[2][8][4] = {};

    const int CPS = K >> 4;           // chunks per segment
    const int T = 3 * CPS;

    // chunk t -> global bf16 offset along the 2K axis
    auto aoffset = [&](int t) -> int {
        int seg = t >> KSH ? (t >> KSH) : 0;    // 0,1,2
        seg = t / CPS;
        int kc = t - seg * CPS;
        int ao = (seg == 2) ? K : 0;
        return ao + kc * 16;
    };
    auto boffset = [&](int t) -> int {
        int seg = t / CPS;
        int kc = t - seg * CPS;
        int bo = (seg == 1) ? K : 0;
        return bo + kc * 16;
    };

    // preload chunk 0
    uint4 pa = *(const uint4*)(Ap + aoffset(0));
    uint4 pb = *(const uint4*)(Bp + boffset(0));
    *(uint2*)&As[0][row][half * 8]     = make_uint2(pa.x, pa.y);
    *(uint2*)&As[0][row][half * 8 + 4] = make_uint2(pa.z, pa.w);
    *(uint2*)&Bs[0][row][half * 8]     = make_uint2(pb.x, pb.y);
    *(uint2*)&Bs[0][row][half * 8 + 4] = make_uint2(pb.z, pb.w);
    __syncthreads();

    for (int t = 0; t < T; t++) {
        int p = t & 1;
        if (t + 1 < T) {
            pa = *(const uint4*)(Ap + aoffset(t + 1));
            pb = *(const uint4*)(Bp + boffset(t + 1));
        }
        // fragments + mma
        uint32_t a[2][4];
#pragma unroll
        for (int mf = 0; mf < 2; mf++) {
            int r0 = warp_m * 32 + mf * 16 + quad;
            a[mf][0] = *(const uint32_t*)&As[p][r0][tid4 * 2];
            a[mf][1] = *(const uint32_t*)&As[p][r0 + 8][tid4 * 2];
            a[mf][2] = *(const uint32_t*)&As[p][r0][tid4 * 2 + 8];
            a[mf][3] = *(const uint32_t*)&As[p][r0 + 8][tid4 * 2 + 8];
        }
#pragma unroll
        for (int nf = 0; nf < 8; nf++) {
            int c0 = warp_n * 64 + nf * 8 + quad;
            uint32_t b0 = *(const uint32_t*)&Bs[p][c0][tid4 * 2];
            uint32_t b1 = *(const uint32_t*)&Bs[p][c0][tid4 * 2 + 8];
            mma16816(acc[0][nf], a[0], b0, b1);
            mma16816(acc[1][nf], a[1], b0, b1);
        }
        if (t + 1 < T) {
            int q = p ^ 1;
            *(uint2*)&As[q][row][half * 8]     = make_uint2(pa.x, pa.y);
            *(uint2*)&As[q][row][half * 8 + 4] = make_uint2(pa.z, pa.w);
            *(uint2*)&Bs[q][row][half * 8]     = make_uint2(pb.x, pb.y);
            *(uint2*)&Bs[q][row][half * 8 + 4] = make_uint2(pb.z, pb.w);
        }
        __syncthreads();
    }

    // epilogue
#pragma unroll
    for (int mf = 0; mf < 2; mf++) {
#pragma unroll
        for (int nf = 0; nf < 8; nf++) {
            int gr = m0 + warp_m * 32 + mf * 16 + quad;
            int gc = n0 + warp_n * 64 + nf * 8 + tid4 * 2;
            float bx = bias[gc], by = bias[gc + 1];
            *(float2*)&Cout[(size_t)gr * N + gc] =
                make_float2(acc[mf][nf][0] + bx, acc[mf][nf][1] + by);
            *(float2*)&Cout[(size_t)(gr + 8) * N + gc] =
                make_float2(acc[mf][nf][2] + bx, acc[mf][nf][3] + by);
        }
    }
}

__global__ void __launch_bounds__(256)
gemm_qkv_t(const float* __restrict__ qkvb) {
    gemm_bf16_body<256, 4>(g_uniS, g_qwS, qkvb, g_qkv, QKV3);
}
__global__ void __launch_bounds__(256)
gemm_final_t(float* __restrict__ out) {
    gemm_bf16_body<512, 5>(g_MS, g_ATS, g_cbias, out, 512);
}

// ---------------------------------------------------------------------------
// Attention: one block per grid position, both contexts (fwd/bwd).
// Writes split-bf16 means into g_MS.
// ---------------------------------------------------------------------------
__global__ void attn_kernel(const float* __restrict__ relb) {
    __shared__ float tok[8][768];    // [ctx*4 + slot][q|k|v]
    __shared__ float osum[8][256];   // [ctx*4 + n][h*32+d]
    __shared__ float btab[72];       // 9 x 8 heads
    int pos = blockIdx.x;
    int b = pos >> 10, yy = (pos >> 5) & 31, xx = pos & 31;
    int tid = threadIdx.x;           // 128

    if (tid < 72) btab[tid] = relb[tid];
#pragma unroll
    for (int s = 0; s < 4; s++) {
        int i = s >> 1, j = s & 1;
        int ry = yy + i; if (ry > 31) ry = 30;
        int rx = xx + j; if (rx > 31) rx = 30;
        const float* src = g_qkv + (size_t)((b * 32 + ry) * 32 + rx) * 768;
        for (int cc = tid; cc < 768; cc += 128) tok[s][cc] = src[cc];
        int by = yy + i; by = (by == 0) ? 1 : by - 1;
        int bx = xx + j; bx = (bx == 0) ? 1 : bx - 1;
        const float* src2 = g_qkv + (size_t)((b * 32 + by) * 32 + bx) * 768;
        for (int cc = tid; cc < 768; cc += 128) tok[4 + s][cc] = src2[cc];
    }
    __syncthreads();

    {
        int ctx = tid >> 6;
        int r = tid & 63;
        int h = r >> 3;
        int n = (r >> 1) & 3;
        int dh = (r & 1) * 16;
        int lane = tid & 31;
        const float scale = 0.17677669529663687f;   // 32^-0.5

        float qreg[32];
#pragma unroll
        for (int dd = 0; dd < 32; dd++)
            qreg[dd] = tok[ctx * 4 + n][h * 32 + ((dd + lane) & 31)];

        int ni = n >> 1, nj = n & 1;
        float sc[4];
#pragma unroll
        for (int m = 0; m < 4; m++) {
            int mi = m >> 1, mj = m & 1;
            int ridx = (ni - mi + 1) * 3 + (nj - mj + 1);
            float a = 0.f;
#pragma unroll
            for (int dd = 0; dd < 32; dd++)
                a += qreg[dd] * tok[ctx * 4 + m][256 + h * 32 + ((dd + lane) & 31)];
            sc[m] = a * scale + btab[ridx * 8 + h];
        }
        float mx = fmaxf(fmaxf(sc[0], sc[1]), fmaxf(sc[2], sc[3]));
        float p0 = expf(sc[0] - mx), p1 = expf(sc[1] - mx);
        float p2 = expf(sc[2] - mx), p3 = expf(sc[3] - mx);
        float inv = 1.f / (p0 + p1 + p2 + p3);
        p0 *= inv; p1 *= inv; p2 *= inv; p3 *= inv;

#pragma unroll
        for (int dd = 0; dd < 16; dd++) {
            int d = dh + ((dd + lane) & 15);
            float o = p0 * tok[ctx * 4 + 0][512 + h * 32 + d]
                    + p1 * tok[ctx * 4 + 1][512 + h * 32 + d]
                    + p2 * tok[ctx * 4 + 2][512 + h * 32 + d]
                    + p3 * tok[ctx * 4 + 3][512 + h * 32 + d];
            osum[ctx * 4 + n][h * 32 + d] = o;
        }
    }
    __syncthreads();

    __nv_bfloat16* dst = g_MS + (size_t)pos * 1024;
    for (int cc = tid; cc < 512; cc += 128) {
        int ctx = cc >> 8, c2 = cc & 255;
        float v = 0.25f * (osum[ctx * 4 + 0][c2] + osum[ctx * 4 + 1][c2] +
                           osum[ctx * 4 + 2][c2] + osum[ctx * 4 + 3][c2]);
        __nv_bfloat16 hi, lo; bf16split(v, hi, lo);
        dst[cc] = hi;
        dst[512 + cc] = lo;
    }
}

// ---------------------------------------------------------------------------
extern "C" void kernel_launch(void* const* d_in, const int* in_sizes, int n_in,
                              void* d_out, int out_size) {
    const float* x      = (const float*)d_in[0];
    const float* uw     = (const float*)d_in[1];
    const float* ub     = (const float*)d_in[2];
    const float* qkvw   = (const float*)d_in[3];
    const float* qkvb   = (const float*)d_in[4];
    const float* relb   = (const float*)d_in[5];
    const float* projw  = (const float*)d_in[6];
    const float* projb  = (const float*)d_in[7];
    const float* mergew = (const float*)d_in[8];
    const float* mergeb = (const float*)d_in[9];
    float* out = (float*)d_out;

    cudaFuncSetAttribute(conv_kernel, cudaFuncAttributeMaxDynamicSharedMemorySize, 32768);

    prep_acomb<<<dim3(32, 32), dim3(16, 16)>>>(projw, mergew);
    prep_cbias<<<4, 128>>>(projb, mergeb, mergew);
    cvt_qkvw<<<768, 256>>>(qkvw);
    conv_kernel<<<1024, 256, 32768>>>(x, uw, ub);
    gemm_qkv_t<<<dim3(QKV3 / 128, NPOS / 128), 256>>>(qkvb);
    attn_kernel<<<NPOS, 128>>>(relb);
    gemm_final_t<<<dim3(512 / 128, NPOS / 128), 256>>>(out);
}

// round 7
// speedup vs baseline: 1.5132x; 1.1616x over previous
#include <cuda_runtime.h>
#include <cuda_fp16.h>
#include <cstdint>

// Problem constants (fixed shapes)
#define BATCH 8
#define NPOS 8192            // 8*32*32
#define HEADS 8
#define HD 32
#define QKV3 768

// Scratch (device globals; no allocation allowed)
__device__ __half g_uniS[NPOS * 512];   // [pos][hi(256)|lo(256)] fp16
__device__ __half g_qwS[QKV3 * 256];    // [n][hi(256)] fp16 (hi only)
__device__ float  g_qkv[NPOS * QKV3];   // fp32 qkv
__device__ __half g_MS[NPOS * 1024];    // [pos][hi(512)|lo(512)]
__device__ __half g_ATS[512 * 512];     // combined proj∘merge, hi only
__device__ float  g_cbias[512];

__device__ __forceinline__ void h16split(float v, __half& hi, __half& lo) {
    hi = __float2half_rn(v);
    lo = __float2half_rn(v - __half2float(hi));
}

// ---------------------------------------------------------------------------
// Prep: AT[d][c2] = sum_e proj_w[e][c2&255] * merge_w[d][(c2>>8)*256 + e]
// ---------------------------------------------------------------------------
__global__ void prep_acomb(const float* __restrict__ proj_w,
                           const float* __restrict__ merge_w) {
    __shared__ float Pt[16][17];
    __shared__ float Mt[16][17];
    int tx = threadIdx.x, ty = threadIdx.y;
    int d0 = blockIdx.y * 16, c0 = blockIdx.x * 16;
    int sel = c0 >> 8;
    int cbase = c0 & 255;
    float acc = 0.f;
    for (int e0 = 0; e0 < 256; e0 += 16) {
        Pt[ty][tx] = proj_w[(e0 + ty) * 256 + cbase + tx];
        Mt[ty][tx] = merge_w[(d0 + ty) * 512 + sel * 256 + e0 + tx];
        __syncthreads();
#pragma unroll
        for (int k = 0; k < 16; k++) acc += Pt[k][tx] * Mt[ty][k];
        __syncthreads();
    }
    g_ATS[(d0 + ty) * 512 + (c0 + tx)] = __float2half_rn(acc);
}

__global__ void prep_cbias(const float* __restrict__ proj_b,
                           const float* __restrict__ merge_b,
                           const float* __restrict__ merge_w) {
    int d = blockIdx.x * 128 + threadIdx.x;
    float acc = merge_b[d];
    for (int e = 0; e < 256; e++)
        acc += proj_b[e] * (merge_w[d * 512 + e] + merge_w[d * 512 + 256 + e]);
    g_cbias[d] = acc;
}

__global__ void cvt_qkvw(const float* __restrict__ w) {
    int i = blockIdx.x * 256 + threadIdx.x;      // 768*256
    g_qwS[i] = __float2half_rn(w[i]);
}

// ---------------------------------------------------------------------------
// Grouped conv, quarter-channel blocks, forced 4 blocks/SM (<=64 regs).
// Epilogue writes fp16 split (hi|lo) into g_uniS.
// ---------------------------------------------------------------------------
__global__ void __launch_bounds__(256, 4)
conv_kernel(const float* __restrict__ x,
            const float* __restrict__ w,
            const float* __restrict__ wb) {
    extern __shared__ float wsh[];   // [64][128]
    int tid = threadIdx.x;           // 256
    int blk = blockIdx.x;            // 1024 = b(8)*oy(32)*cq(4)
    int cq = blk & 3;
    int oy = (blk >> 2) & 31;
    int b = blk >> 7;

    for (int idx = tid; idx < 8192; idx += 256) {
        int t = idx >> 7;            // 0..63
        int r = idx & 127;
        int cl = r >> 1, i = r & 1;
        wsh[idx] = w[(cq * 64 + cl) * 128 + i * 64 + t];
    }
    __syncthreads();

    int cg = tid & 31;
    int oxq = tid >> 5;              // 0..7
    int ox0 = oxq * 4;
    int cout0 = cq * 64 + cg * 2;
    int cin0 = cq * 128 + cg * 4;

    float b0 = wb[cout0], b1 = wb[cout0 + 1];
    float a0x = b0, a0y = b1, a1x = b0, a1y = b1;
    float a2x = b0, a2y = b1, a3x = b0, a3y = b1;

#pragma unroll
    for (int kh = 0; kh < 8; kh++) {
        const float* xr =
            x + ((size_t)(b * 256 + oy * 8 + kh) * 256 + ox0 * 8) * 512 + cin0;
#pragma unroll
        for (int kw = 0; kw < 8; kw++) {
            float4 wv = *(const float4*)&wsh[(kh * 8 + kw) * 128 + cg * 4];
            float4 x0 = *(const float4*)(xr + (0 * 8 + kw) * 512);
            float4 x1 = *(const float4*)(xr + (1 * 8 + kw) * 512);
            float4 x2 = *(const float4*)(xr + (2 * 8 + kw) * 512);
            float4 x3 = *(const float4*)(xr + (3 * 8 + kw) * 512);
            a0x += x0.x * wv.x + x0.y * wv.y;  a0y += x0.z * wv.z + x0.w * wv.w;
            a1x += x1.x * wv.x + x1.y * wv.y;  a1y += x1.z * wv.z + x1.w * wv.w;
            a2x += x2.x * wv.x + x2.y * wv.y;  a2y += x2.z * wv.z + x2.w * wv.w;
            a3x += x3.x * wv.x + x3.y * wv.y;  a3y += x3.z * wv.z + x3.w * wv.w;
        }
    }
    int pos0 = (b * 32 + oy) * 32 + ox0;
    float av[4][2] = {{a0x, a0y}, {a1x, a1y}, {a2x, a2y}, {a3x, a3y}};
#pragma unroll
    for (int u = 0; u < 4; u++) {
        __half h0, l0, h1, l1;
        h16split(av[u][0], h0, l0);
        h16split(av[u][1], h1, l1);
        size_t base = (size_t)(pos0 + u) * 512;
        *(__half2*)&g_uniS[base + cout0]       = __halves2half2(h0, h1);
        *(__half2*)&g_uniS[base + 256 + cout0] = __halves2half2(l0, l1);
    }
}

// ---------------------------------------------------------------------------
// 2-segment fp16 tensor-core GEMM: C = A@B^T + bias
//   A2: (M, 2K) fp16 = [hi|lo] planes (A exact to 2^-22)
//   B : (N, K)  fp16 hi-only; C error ~ A*Blo ~ 2^-11 rms
// Block tile 128x128, 8 warps (32x64 each), stage k-chunk 32 (2 x k16),
// smem double buffered, one sync per stage.
// ---------------------------------------------------------------------------
__device__ __forceinline__ void mma16816h(float* d, const uint32_t* a,
                                          uint32_t b0, uint32_t b1) {
    asm volatile(
        "mma.sync.aligned.m16n8k16.row.col.f32.f16.f16.f32 "
        "{%0,%1,%2,%3}, {%4,%5,%6,%7}, {%8,%9}, {%0,%1,%2,%3};\n"
        : "+f"(d[0]), "+f"(d[1]), "+f"(d[2]), "+f"(d[3])
        : "r"(a[0]), "r"(a[1]), "r"(a[2]), "r"(a[3]), "r"(b0), "r"(b1));
}

template <int K>   // per-plane K: 256 (qkv) or 512 (final)
__device__ __forceinline__ void gemm_h2_body(const __half* __restrict__ A2,
                                             const __half* __restrict__ B,
                                             const float* __restrict__ bias,
                                             float* __restrict__ Cout, int N) {
    __shared__ __half As[2][128][40];   // 32 data + 8 pad
    __shared__ __half Bs[2][128][40];
    int tid = threadIdx.x;              // 256
    int m0 = blockIdx.y * 128, n0 = blockIdx.x * 128;

    int row = tid >> 1;                 // 0..127
    int half = tid & 1;                 // 16-half (32B) chunk selector
    const __half* Ap = A2 + (size_t)(m0 + row) * (2 * K) + half * 16;
    const __half* Bp = B + (size_t)(n0 + row) * K + half * 16;

    int warp = tid >> 5, lane = tid & 31;
    int warp_m = warp & 3, warp_n = warp >> 2;
    int quad = lane >> 2, tid4 = lane & 3;

    float acc[2][8][4] = {};

    const int T = K / 16;               // stages (each covers 32 of 2K axis)
    auto bofs = [&](int s) -> int {     // B k-offset with hi-plane wrap
        int o = s * 32;
        return (o >= K) ? (o - K) : o;
    };

    // preload stage 0
    uint4 pa0 = *(const uint4*)(Ap + 0);
    uint4 pa1 = *(const uint4*)(Ap + 8);
    uint4 pb0 = *(const uint4*)(Bp + 0);
    uint4 pb1 = *(const uint4*)(Bp + 8);
    *(uint4*)&As[0][row][half * 16]     = pa0;
    *(uint4*)&As[0][row][half * 16 + 8] = pa1;
    *(uint4*)&Bs[0][row][half * 16]     = pb0;
    *(uint4*)&Bs[0][row][half * 16 + 8] = pb1;
    __syncthreads();

    for (int t = 0; t < T; t++) {
        int p = t & 1;
        if (t + 1 < T) {
            pa0 = *(const uint4*)(Ap + (t + 1) * 32);
            pa1 = *(const uint4*)(Ap + (t + 1) * 32 + 8);
            pb0 = *(const uint4*)(Bp + bofs(t + 1));
            pb1 = *(const uint4*)(Bp + bofs(t + 1) + 8);
        }
#pragma unroll
        for (int kk = 0; kk < 32; kk += 16) {
            uint32_t a[2][4];
#pragma unroll
            for (int mf = 0; mf < 2; mf++) {
                int r0 = warp_m * 32 + mf * 16 + quad;
                a[mf][0] = *(const uint32_t*)&As[p][r0][kk + tid4 * 2];
                a[mf][1] = *(const uint32_t*)&As[p][r0 + 8][kk + tid4 * 2];
                a[mf][2] = *(const uint32_t*)&As[p][r0][kk + tid4 * 2 + 8];
                a[mf][3] = *(const uint32_t*)&As[p][r0 + 8][kk + tid4 * 2 + 8];
            }
#pragma unroll
            for (int nf = 0; nf < 8; nf++) {
                int c0 = warp_n * 64 + nf * 8 + quad;
                uint32_t b0 = *(const uint32_t*)&Bs[p][c0][kk + tid4 * 2];
                uint32_t b1 = *(const uint32_t*)&Bs[p][c0][kk + tid4 * 2 + 8];
                mma16816h(acc[0][nf], a[0], b0, b1);
                mma16816h(acc[1][nf], a[1], b0, b1);
            }
        }
        if (t + 1 < T) {
            int q = p ^ 1;
            *(uint4*)&As[q][row][half * 16]     = pa0;
            *(uint4*)&As[q][row][half * 16 + 8] = pa1;
            *(uint4*)&Bs[q][row][half * 16]     = pb0;
            *(uint4*)&Bs[q][row][half * 16 + 8] = pb1;
        }
        __syncthreads();
    }

    // epilogue
#pragma unroll
    for (int mf = 0; mf < 2; mf++) {
#pragma unroll
        for (int nf = 0; nf < 8; nf++) {
            int gr = m0 + warp_m * 32 + mf * 16 + quad;
            int gc = n0 + warp_n * 64 + nf * 8 + tid4 * 2;
            float bx = bias[gc], by = bias[gc + 1];
            *(float2*)&Cout[(size_t)gr * N + gc] =
                make_float2(acc[mf][nf][0] + bx, acc[mf][nf][1] + by);
            *(float2*)&Cout[(size_t)(gr + 8) * N + gc] =
                make_float2(acc[mf][nf][2] + bx, acc[mf][nf][3] + by);
        }
    }
}

__global__ void __launch_bounds__(256)
gemm_qkv_t(const float* __restrict__ qkvb) {
    gemm_h2_body<256>(g_uniS, g_qwS, qkvb, g_qkv, QKV3);
}
__global__ void __launch_bounds__(256)
gemm_final_t(float* __restrict__ out) {
    gemm_h2_body<512>(g_MS, g_ATS, g_cbias, out, 512);
}

// ---------------------------------------------------------------------------
// Attention: one block per grid position, both contexts (fwd/bwd).
// Writes fp16 split means into g_MS.
// ---------------------------------------------------------------------------
__global__ void attn_kernel(const float* __restrict__ relb) {
    __shared__ float tok[8][768];    // [ctx*4 + slot][q|k|v]
    __shared__ float osum[8][256];   // [ctx*4 + n][h*32+d]
    __shared__ float btab[72];       // 9 x 8 heads
    int pos = blockIdx.x;
    int b = pos >> 10, yy = (pos >> 5) & 31, xx = pos & 31;
    int tid = threadIdx.x;           // 128

    if (tid < 72) btab[tid] = relb[tid];
#pragma unroll
    for (int s = 0; s < 4; s++) {
        int i = s >> 1, j = s & 1;
        int ry = yy + i; if (ry > 31) ry = 30;
        int rx = xx + j; if (rx > 31) rx = 30;
        const float* src = g_qkv + (size_t)((b * 32 + ry) * 32 + rx) * 768;
        for (int cc = tid; cc < 768; cc += 128) tok[s][cc] = src[cc];
        int by = yy + i; by = (by == 0) ? 1 : by - 1;
        int bx = xx + j; bx = (bx == 0) ? 1 : bx - 1;
        const float* src2 = g_qkv + (size_t)((b * 32 + by) * 32 + bx) * 768;
        for (int cc = tid; cc < 768; cc += 128) tok[4 + s][cc] = src2[cc];
    }
    __syncthreads();

    {
        int ctx = tid >> 6;
        int r = tid & 63;
        int h = r >> 3;
        int n = (r >> 1) & 3;
        int dh = (r & 1) * 16;
        int lane = tid & 31;
        const float scale = 0.17677669529663687f;   // 32^-0.5

        float qreg[32];
#pragma unroll
        for (int dd = 0; dd < 32; dd++)
            qreg[dd] = tok[ctx * 4 + n][h * 32 + ((dd + lane) & 31)];

        int ni = n >> 1, nj = n & 1;
        float sc[4];
#pragma unroll
        for (int m = 0; m < 4; m++) {
            int mi = m >> 1, mj = m & 1;
            int ridx = (ni - mi + 1) * 3 + (nj - mj + 1);
            float a = 0.f;
#pragma unroll
            for (int dd = 0; dd < 32; dd++)
                a += qreg[dd] * tok[ctx * 4 + m][256 + h * 32 + ((dd + lane) & 31)];
            sc[m] = a * scale + btab[ridx * 8 + h];
        }
        float mx = fmaxf(fmaxf(sc[0], sc[1]), fmaxf(sc[2], sc[3]));
        float p0 = expf(sc[0] - mx), p1 = expf(sc[1] - mx);
        float p2 = expf(sc[2] - mx), p3 = expf(sc[3] - mx);
        float inv = 1.f / (p0 + p1 + p2 + p3);
        p0 *= inv; p1 *= inv; p2 *= inv; p3 *= inv;

#pragma unroll
        for (int dd = 0; dd < 16; dd++) {
            int d = dh + ((dd + lane) & 15);
            float o = p0 * tok[ctx * 4 + 0][512 + h * 32 + d]
                    + p1 * tok[ctx * 4 + 1][512 + h * 32 + d]
                    + p2 * tok[ctx * 4 + 2][512 + h * 32 + d]
                    + p3 * tok[ctx * 4 + 3][512 + h * 32 + d];
            osum[ctx * 4 + n][h * 32 + d] = o;
        }
    }
    __syncthreads();

    __half* dst = g_MS + (size_t)pos * 1024;
    for (int cc = tid; cc < 512; cc += 128) {
        int ctx = cc >> 8, c2 = cc & 255;
        float v = 0.25f * (osum[ctx * 4 + 0][c2] + osum[ctx * 4 + 1][c2] +
                           osum[ctx * 4 + 2][c2] + osum[ctx * 4 + 3][c2]);
        __half hi, lo; h16split(v, hi, lo);
        dst[cc] = hi;
        dst[512 + cc] = lo;
    }
}

// ---------------------------------------------------------------------------
extern "C" void kernel_launch(void* const* d_in, const int* in_sizes, int n_in,
                              void* d_out, int out_size) {
    const float* x      = (const float*)d_in[0];
    const float* uw     = (const float*)d_in[1];
    const float* ub     = (const float*)d_in[2];
    const float* qkvw   = (const float*)d_in[3];
    const float* qkvb   = (const float*)d_in[4];
    const float* relb   = (const float*)d_in[5];
    const float* projw  = (const float*)d_in[6];
    const float* projb  = (const float*)d_in[7];
    const float* mergew = (const float*)d_in[8];
    const float* mergeb = (const float*)d_in[9];
    float* out = (float*)d_out;

    cudaFuncSetAttribute(conv_kernel, cudaFuncAttributeMaxDynamicSharedMemorySize, 32768);

    prep_acomb<<<dim3(32, 32), dim3(16, 16)>>>(projw, mergew);
    prep_cbias<<<4, 128>>>(projb, mergeb, mergew);
    cvt_qkvw<<<768, 256>>>(qkvw);
    conv_kernel<<<1024, 256, 32768>>>(x, uw, ub);
    gemm_qkv_t<<<dim3(QKV3 / 128, NPOS / 128), 256>>>(qkvb);
    attn_kernel<<<NPOS, 128>>>(relb);
    gemm_final_t<<<dim3(512 / 128, NPOS / 128), 256>>>(out);
}

// round 8
// speedup vs baseline: 1.6927x; 1.1186x over previous
#include <cuda_runtime.h>
#include <cuda_fp16.h>
#include <cstdint>

#define NPOS 8192            // 8*32*32
#define QKV3 768

// Scratch (device globals; no allocation allowed)
__device__ __half g_uniS[NPOS * 512];   // [pos][hi(256)|lo(256)] fp16
__device__ __half g_qwS[QKV3 * 256];    // [n][hi(256)] fp16 (hi only)
__device__ float  g_qkv[NPOS * QKV3];   // fp32 qkv
__device__ __half g_MS[NPOS * 1024];    // [pos][hi(512)|lo(512)]
__device__ __half g_ATS[512 * 512];     // combined proj∘merge, hi only
__device__ float  g_cbias[512];

__device__ __forceinline__ void h16split(float v, __half& hi, __half& lo) {
    hi = __float2half_rn(v);
    lo = __float2half_rn(v - __half2float(hi));
}

// ---------------------------------------------------------------------------
// Prep kernels
// ---------------------------------------------------------------------------
__global__ void prep_acomb(const float* __restrict__ proj_w,
                           const float* __restrict__ merge_w) {
    __shared__ float Pt[16][17];
    __shared__ float Mt[16][17];
    int tx = threadIdx.x, ty = threadIdx.y;
    int d0 = blockIdx.y * 16, c0 = blockIdx.x * 16;
    int sel = c0 >> 8;
    int cbase = c0 & 255;
    float acc = 0.f;
    for (int e0 = 0; e0 < 256; e0 += 16) {
        Pt[ty][tx] = proj_w[(e0 + ty) * 256 + cbase + tx];
        Mt[ty][tx] = merge_w[(d0 + ty) * 512 + sel * 256 + e0 + tx];
        __syncthreads();
#pragma unroll
        for (int k = 0; k < 16; k++) acc += Pt[k][tx] * Mt[ty][k];
        __syncthreads();
    }
    g_ATS[(d0 + ty) * 512 + (c0 + tx)] = __float2half_rn(acc);
}

__global__ void prep_cbias(const float* __restrict__ proj_b,
                           const float* __restrict__ merge_b,
                           const float* __restrict__ merge_w) {
    int d = blockIdx.x * 128 + threadIdx.x;
    float acc = merge_b[d];
    for (int e = 0; e < 256; e++)
        acc += proj_b[e] * (merge_w[d * 512 + e] + merge_w[d * 512 + 256 + e]);
    g_cbias[d] = acc;
}

__global__ void cvt_qkvw(const float* __restrict__ w) {
    int i = blockIdx.x * 256 + threadIdx.x;      // 768*256
    g_qwS[i] = __float2half_rn(w[i]);
}

// ---------------------------------------------------------------------------
// Grouped conv (unchanged from R7: 75% DRAM, near plateau)
// ---------------------------------------------------------------------------
__global__ void __launch_bounds__(256, 4)
conv_kernel(const float* __restrict__ x,
            const float* __restrict__ w,
            const float* __restrict__ wb) {
    extern __shared__ float wsh[];   // [64][128]
    int tid = threadIdx.x;
    int blk = blockIdx.x;            // 1024 = b(8)*oy(32)*cq(4)
    int cq = blk & 3;
    int oy = (blk >> 2) & 31;
    int b = blk >> 7;

    for (int idx = tid; idx < 8192; idx += 256) {
        int t = idx >> 7;
        int r = idx & 127;
        int cl = r >> 1, i = r & 1;
        wsh[idx] = w[(cq * 64 + cl) * 128 + i * 64 + t];
    }
    __syncthreads();

    int cg = tid & 31;
    int oxq = tid >> 5;
    int ox0 = oxq * 4;
    int cout0 = cq * 64 + cg * 2;
    int cin0 = cq * 128 + cg * 4;

    float b0 = wb[cout0], b1 = wb[cout0 + 1];
    float a0x = b0, a0y = b1, a1x = b0, a1y = b1;
    float a2x = b0, a2y = b1, a3x = b0, a3y = b1;

#pragma unroll
    for (int kh = 0; kh < 8; kh++) {
        const float* xr =
            x + ((size_t)(b * 256 + oy * 8 + kh) * 256 + ox0 * 8) * 512 + cin0;
#pragma unroll
        for (int kw = 0; kw < 8; kw++) {
            float4 wv = *(const float4*)&wsh[(kh * 8 + kw) * 128 + cg * 4];
            float4 x0 = *(const float4*)(xr + (0 * 8 + kw) * 512);
            float4 x1 = *(const float4*)(xr + (1 * 8 + kw) * 512);
            float4 x2 = *(const float4*)(xr + (2 * 8 + kw) * 512);
            float4 x3 = *(const float4*)(xr + (3 * 8 + kw) * 512);
            a0x += x0.x * wv.x + x0.y * wv.y;  a0y += x0.z * wv.z + x0.w * wv.w;
            a1x += x1.x * wv.x + x1.y * wv.y;  a1y += x1.z * wv.z + x1.w * wv.w;
            a2x += x2.x * wv.x + x2.y * wv.y;  a2y += x2.z * wv.z + x2.w * wv.w;
            a3x += x3.x * wv.x + x3.y * wv.y;  a3y += x3.z * wv.z + x3.w * wv.w;
        }
    }
    int pos0 = (b * 32 + oy) * 32 + ox0;
    float av[4][2] = {{a0x, a0y}, {a1x, a1y}, {a2x, a2y}, {a3x, a3y}};
#pragma unroll
    for (int u = 0; u < 4; u++) {
        __half h0, l0, h1, l1;
        h16split(av[u][0], h0, l0);
        h16split(av[u][1], h1, l1);
        size_t base = (size_t)(pos0 + u) * 512;
        *(__half2*)&g_uniS[base + cout0]       = __halves2half2(h0, h1);
        *(__half2*)&g_uniS[base + 256 + cout0] = __halves2half2(l0, l1);
    }
}

// ---------------------------------------------------------------------------
// 2-segment fp16 tensor-core GEMM with cp.async + ldmatrix.
//   A2: (M, 2K) fp16 [hi|lo] planes; B: (N, K) fp16 hi-only.
// Block 128x128, 8 warps (32x64 each), stage k=32, double buffered.
// ---------------------------------------------------------------------------
__device__ __forceinline__ uint32_t smem_u32(const void* p) {
    return (uint32_t)__cvta_generic_to_shared(p);
}
__device__ __forceinline__ void cp16(uint32_t dst, const void* src) {
    asm volatile("cp.async.cg.shared.global [%0], [%1], 16;\n" :: "r"(dst), "l"(src));
}
__device__ __forceinline__ void cp_commit() {
    asm volatile("cp.async.commit_group;\n" ::: "memory");
}
__device__ __forceinline__ void cp_wait0() {
    asm volatile("cp.async.wait_group 0;\n" ::: "memory");
}
__device__ __forceinline__ void ldsm_x4(uint32_t& r0, uint32_t& r1, uint32_t& r2,
                                        uint32_t& r3, uint32_t addr) {
    asm volatile("ldmatrix.sync.aligned.m8n8.x4.shared.b16 {%0,%1,%2,%3}, [%4];\n"
                 : "=r"(r0), "=r"(r1), "=r"(r2), "=r"(r3) : "r"(addr));
}
__device__ __forceinline__ void mma16816h(float* d, const uint32_t* a,
                                          uint32_t b0, uint32_t b1) {
    asm volatile(
        "mma.sync.aligned.m16n8k16.row.col.f32.f16.f16.f32 "
        "{%0,%1,%2,%3}, {%4,%5,%6,%7}, {%8,%9}, {%0,%1,%2,%3};\n"
        : "+f"(d[0]), "+f"(d[1]), "+f"(d[2]), "+f"(d[3])
        : "r"(a[0]), "r"(a[1]), "r"(a[2]), "r"(a[3]), "r"(b0), "r"(b1));
}

template <int K>   // per-plane K: 256 (qkv) or 512 (final)
__device__ __forceinline__ void gemm_h2_body(const __half* __restrict__ A2,
                                             const __half* __restrict__ B,
                                             const float* __restrict__ bias,
                                             float* __restrict__ Cout, int N) {
    __shared__ __half As[2][128][40];   // 32 data + 8 pad halves (80B rows)
    __shared__ __half Bs[2][128][40];
    int tid = threadIdx.x;              // 256
    int m0 = blockIdx.y * 128, n0 = blockIdx.x * 128;

    int row = tid >> 1;                 // 0..127
    int ch = (tid & 1) * 16;            // half offset within 32-half stage row
    const __half* Apg = A2 + (size_t)(m0 + row) * (2 * K) + ch;
    const __half* Bpg = B + (size_t)(n0 + row) * K + ch;

    int warp = tid >> 5, lane = tid & 31;
    int wm = (warp & 3) * 32, wn = (warp >> 2) * 64;
    int quad = lane >> 2, tid4 = lane & 3;
    int lrow = lane & 15, lcol = (lane >> 4) * 8;

    float acc[2][8][4] = {};

    const int T = 2 * K / 32;
    auto bofs = [&](int t) -> int { int o = t * 32; return (o >= K) ? o - K : o; };
    auto issue = [&](int t, int buf) {
        uint32_t da = smem_u32(&As[buf][row][ch]);
        cp16(da, Apg + t * 32);
        cp16(da + 16, Apg + t * 32 + 8);
        uint32_t db = smem_u32(&Bs[buf][row][ch]);
        cp16(db, Bpg + bofs(t) - ch + ch);   // Bpg already includes +ch
        cp16(db + 16, Bpg + bofs(t) + 8);
    };

    issue(0, 0); cp_commit(); cp_wait0(); __syncthreads();

    for (int t = 0; t < T; t++) {
        int p = t & 1;
        if (t + 1 < T) { issue(t + 1, p ^ 1); cp_commit(); }
#pragma unroll
        for (int kk = 0; kk < 32; kk += 16) {
            uint32_t a0[4], a1[4];
            ldsm_x4(a0[0], a0[1], a0[2], a0[3],
                    smem_u32(&As[p][wm + lrow][kk + lcol]));
            ldsm_x4(a1[0], a1[1], a1[2], a1[3],
                    smem_u32(&As[p][wm + 16 + lrow][kk + lcol]));
#pragma unroll
            for (int nfp = 0; nfp < 4; nfp++) {
                uint32_t b0, b1, b2, b3;
                ldsm_x4(b0, b1, b2, b3,
                        smem_u32(&Bs[p][wn + nfp * 16 + lrow][kk + lcol]));
                mma16816h(acc[0][2 * nfp],     a0, b0, b2);
                mma16816h(acc[0][2 * nfp + 1], a0, b1, b3);
                mma16816h(acc[1][2 * nfp],     a1, b0, b2);
                mma16816h(acc[1][2 * nfp + 1], a1, b1, b3);
            }
        }
        if (t + 1 < T) cp_wait0();
        __syncthreads();
    }

    // epilogue
#pragma unroll
    for (int mf = 0; mf < 2; mf++) {
#pragma unroll
        for (int nf = 0; nf < 8; nf++) {
            int gr = m0 + wm + mf * 16 + quad;
            int gc = n0 + wn + nf * 8 + tid4 * 2;
            float bx = bias[gc], by = bias[gc + 1];
            *(float2*)&Cout[(size_t)gr * N + gc] =
                make_float2(acc[mf][nf][0] + bx, acc[mf][nf][1] + by);
            *(float2*)&Cout[(size_t)(gr + 8) * N + gc] =
                make_float2(acc[mf][nf][2] + bx, acc[mf][nf][3] + by);
        }
    }
}

__global__ void __launch_bounds__(256)
gemm_qkv_t(const float* __restrict__ qkvb) {
    gemm_h2_body<256>(g_uniS, g_qwS, qkvb, g_qkv, QKV3);
}
__global__ void __launch_bounds__(256)
gemm_final_t(float* __restrict__ out) {
    gemm_h2_body<512>(g_MS, g_ATS, g_cbias, out, 512);
}

// ---------------------------------------------------------------------------
// Attention, tiled: block = 4x4 positions, smem holds 6x6 qkv neighborhood.
// Thread = (pos 16, ctx 2, head 8). Mean over queries commuted into pbar,
// single PV pass. h-skewed d indexing to spread smem banks.
// ---------------------------------------------------------------------------
#define TSTRIDE 776
__global__ void __launch_bounds__(256)
attn_kernel(const float* __restrict__ relb) {
    extern __shared__ float tok[];       // [36][TSTRIDE]
    __shared__ float btab[72];
    int blk = blockIdx.x;                // 512 = b(8) * ty(8) * tx(8)
    int b = blk >> 6, tyl = (blk >> 3) & 7, txl = blk & 7;
    int y0 = tyl * 4, x0 = txl * 4;
    int tid = threadIdx.x;               // 256

    if (tid < 72) btab[tid] = relb[tid];

    // load 6x6 neighborhood (clamped) of qkv rows
    for (int idx = tid; idx < 36 * 192; idx += 256) {
        int rr = idx / 192, q4 = idx % 192;
        int rdy = rr / 6, rdx = rr % 6;
        int gy = min(max(y0 - 1 + rdy, 0), 31);
        int gx = min(max(x0 - 1 + rdx, 0), 31);
        const float4* src =
            (const float4*)(g_qkv + (size_t)((b * 32 + gy) * 32 + gx) * 768);
        *(float4*)&tok[rr * TSTRIDE + q4 * 4] = src[q4];
    }
    __syncthreads();

    int h = tid & 7, ctx = (tid >> 3) & 1, p = tid >> 4;
    int ty = p >> 2, tx = p & 3;

    int rows[4];
#pragma unroll
    for (int s = 0; s < 4; s++) {
        int i = s >> 1, j = s & 1;
        int r, c;
        if (ctx == 0) {                  // fwd: >31 -> 30
            int gy = y0 + ty + i; if (gy > 31) gy = 30; r = gy - y0 + 1;
            int gx = x0 + tx + j; if (gx > 31) gx = 30; c = gx - x0 + 1;
        } else {                         // bwd: 0 -> 1, else -1
            int gy = y0 + ty + i; gy = (gy == 0) ? 1 : gy - 1; r = gy - y0 + 1;
            int gx = x0 + tx + j; gx = (gx == 0) ? 1 : gx - 1; c = gx - x0 + 1;
        }
        rows[s] = (r * 6 + c) * TSTRIDE;
    }

    const float scale = 0.17677669529663687f;   // 32^-0.5
    int hb = h * 32;
    float s[4][4] = {};
#pragma unroll
    for (int dd = 0; dd < 32; dd++) {
        int d = (dd + h * 4) & 31;
        float qv[4], kv[4];
#pragma unroll
        for (int n = 0; n < 4; n++) qv[n] = tok[rows[n] + hb + d];
#pragma unroll
        for (int m = 0; m < 4; m++) kv[m] = tok[rows[m] + 256 + hb + d];
#pragma unroll
        for (int n = 0; n < 4; n++)
#pragma unroll
            for (int m = 0; m < 4; m++) s[n][m] += qv[n] * kv[m];
    }

    float pbar[4] = {};
#pragma unroll
    for (int n = 0; n < 4; n++) {
        int ni = n >> 1, nj = n & 1;
        float sc[4];
#pragma unroll
        for (int m = 0; m < 4; m++) {
            int mi = m >> 1, mj = m & 1;
            sc[m] = s[n][m] * scale + btab[((ni - mi + 1) * 3 + (nj - mj + 1)) * 8 + h];
        }
        float mx = fmaxf(fmaxf(sc[0], sc[1]), fmaxf(sc[2], sc[3]));
        float e0 = expf(sc[0] - mx), e1 = expf(sc[1] - mx);
        float e2 = expf(sc[2] - mx), e3 = expf(sc[3] - mx);
        float inv = 1.f / (e0 + e1 + e2 + e3);
        pbar[0] += e0 * inv; pbar[1] += e1 * inv;
        pbar[2] += e2 * inv; pbar[3] += e3 * inv;
    }
#pragma unroll
    for (int m = 0; m < 4; m++) pbar[m] *= 0.25f;

    int pos = (b * 32 + y0 + ty) * 32 + x0 + tx;
    __half* dst = g_MS + (size_t)pos * 1024 + ctx * 256 + hb;
#pragma unroll
    for (int dd = 0; dd < 32; dd++) {
        int d = (dd + h * 4) & 31;
        float o = pbar[0] * tok[rows[0] + 512 + hb + d]
                + pbar[1] * tok[rows[1] + 512 + hb + d]
                + pbar[2] * tok[rows[2] + 512 + hb + d]
                + pbar[3] * tok[rows[3] + 512 + hb + d];
        __half hi = __float2half_rn(o);
        dst[d] = hi;
        dst[512 + d] = __float2half_rn(o - __half2float(hi));
    }
}

// ---------------------------------------------------------------------------
extern "C" void kernel_launch(void* const* d_in, const int* in_sizes, int n_in,
                              void* d_out, int out_size) {
    const float* x      = (const float*)d_in[0];
    const float* uw     = (const float*)d_in[1];
    const float* ub     = (const float*)d_in[2];
    const float* qkvw   = (const float*)d_in[3];
    const float* qkvb   = (const float*)d_in[4];
    const float* relb   = (const float*)d_in[5];
    const float* projw  = (const float*)d_in[6];
    const float* projb  = (const float*)d_in[7];
    const float* mergew = (const float*)d_in[8];
    const float* mergeb = (const float*)d_in[9];
    float* out = (float*)d_out;

    cudaFuncSetAttribute(conv_kernel, cudaFuncAttributeMaxDynamicSharedMemorySize, 32768);
    cudaFuncSetAttribute(attn_kernel, cudaFuncAttributeMaxDynamicSharedMemorySize,
                         36 * TSTRIDE * 4);

    prep_acomb<<<dim3(32, 32), dim3(16, 16)>>>(projw, mergew);
    prep_cbias<<<4, 128>>>(projb, mergeb, mergew);
    cvt_qkvw<<<768, 256>>>(qkvw);
    conv_kernel<<<1024, 256, 32768>>>(x, uw, ub);
    gemm_qkv_t<<<dim3(QKV3 / 128, NPOS / 128), 256>>>(qkvb);
    attn_kernel<<<512, 256, 36 * TSTRIDE * 4>>>(relb);
    gemm_final_t<<<dim3(512 / 128, NPOS / 128), 256>>>(out);
}